// round 10
// baseline (speedup 1.0000x reference)
#include <cuda_runtime.h>
#include <math.h>
#include <stdint.h>

#define BB   4
#define TT   2048
#define HIDD 2048
#define NHH  16
#define HDD  128
#define MTOT (BB*TT)
#define NQKV (3*HIDD)
#define NX   (MTOT*HIDD)
#define NW1  (NQKV*HIDD)
#define NW2  (HIDD*HIDD)
#define SCALE 0.08838834764831845f

__device__ float g_q[BB*NHH*TT*HDD];
__device__ float g_k[BB*NHH*TT*HDD];
__device__ float g_v[BB*NHH*HDD*TT];   // TRANSPOSED: [bh][d][t]
__device__ float g_attn[BB*TT*HIDD];
__device__ float g_x[NX];
__device__ float g_w1[NW1];
__device__ float g_w2[NW2];

__device__ __forceinline__ uint32_t f2tf(float f) {
    uint32_t u; asm("cvt.rna.tf32.f32 %0, %1;" : "=r"(u) : "f"(f)); return u;
}
__device__ __forceinline__ float rtf(float f) { return __uint_as_float(f2tf(f)); }

__device__ __forceinline__ void mma_tf32(float* c, const uint32_t* a, const uint32_t* b) {
    asm volatile(
        "mma.sync.aligned.m16n8k8.row.col.f32.tf32.tf32.f32 "
        "{%0,%1,%2,%3}, {%4,%5,%6,%7}, {%8,%9}, {%0,%1,%2,%3};\n"
        : "+f"(c[0]), "+f"(c[1]), "+f"(c[2]), "+f"(c[3])
        : "r"(a[0]), "r"(a[1]), "r"(a[2]), "r"(a[3]), "r"(b[0]), "r"(b[1]));
}
__device__ __forceinline__ void cp16(void* s, const void* g) {
    uint32_t sa = (uint32_t)__cvta_generic_to_shared(s);
    asm volatile("cp.async.cg.shared.global [%0], [%1], 16;" :: "r"(sa), "l"(g));
}
#define CPC    asm volatile("cp.async.commit_group;")
#define CPW(n) asm volatile("cp.async.wait_group %0;" :: "n"(n))

__device__ __forceinline__ void ldsm4(uint32_t& r0, uint32_t& r1,
                                      uint32_t& r2, uint32_t& r3, uint32_t a) {
    asm volatile("ldmatrix.sync.aligned.m8n8.x4.shared.b16 {%0,%1,%2,%3}, [%4];"
        : "=r"(r0), "=r"(r1), "=r"(r2), "=r"(r3) : "r"(a));
}

// ---------------- pre-round inputs to tf32 ----------------
__global__ void round_k(const float* __restrict__ in, float* __restrict__ outp) {
    int i = (blockIdx.x * 256 + threadIdx.x) * 4;
    float4 v = *(const float4*)(in + i);
    *(float4*)(outp + i) = make_float4(rtf(v.x), rtf(v.y), rtf(v.z), rtf(v.w));
}

// ---------------- tf32 GEMM, 256x128 block, 3-stage cp.async, k-chunk 32 ----
#define GST 36
#define GAWA (256*GST)
#define GAWB (128*GST)
#define GSTG (GAWA+GAWB)
#define GEMM_SMEM (3 * GSTG * 4)   // 165888 B, 1 CTA/SM

template<int MODE>
__global__ __launch_bounds__(512, 1)
void gemm_tf32(const float* __restrict__ cosb, const float* __restrict__ sinb,
               const float* __restrict__ bias, float* __restrict__ Cout)
{
    extern __shared__ float gs[];
    const int tid  = threadIdx.x;
    const int w    = tid >> 5, lane = tid & 31;
    const int g    = lane >> 2, tg = lane & 3;
    const int wm   = w >> 2, wn = w & 3;            // 4 x 4 warps
    const int bm   = blockIdx.y << 8, bn = blockIdx.x << 7;
    const int r2 = tid >> 3;            // 0..63
    const int c2 = (tid & 7) << 2;      // 0,4,..,28

    const int rowA = wm * 64 + (lane & 7) + ((lane >> 3) & 1) * 8;
    const int colA = (lane >> 4) * 4;
    const int rowB = wn * 32 + (lane & 7) + (lane >> 4) * 8;
    const int colB = ((lane >> 3) & 1) * 4;

    const float* Ap = ((MODE == 0) ? g_x  : g_attn) + (size_t)(bm + r2) * HIDD + c2;
    const float* Bp = ((MODE == 0) ? g_w1 : g_w2)   + (size_t)(bn + r2) * HIDD + c2;

    float acc[4][4][4];
#pragma unroll
    for (int i = 0; i < 4; i++)
#pragma unroll
        for (int j = 0; j < 4; j++)
#pragma unroll
            for (int q = 0; q < 4; q++) acc[i][j][q] = 0.f;

#pragma unroll
    for (int c = 0; c < 2; c++) {
        float* sA = gs + c * GSTG; float* sB = sA + GAWA;
#pragma unroll
        for (int p = 0; p < 4; p++)
            cp16(&sA[(r2 + p * 64) * GST + c2], Ap + (size_t)(p * 64) * HIDD + c * 32);
#pragma unroll
        for (int p = 0; p < 2; p++)
            cp16(&sB[(r2 + p * 64) * GST + c2], Bp + (size_t)(p * 64) * HIDD + c * 32);
        CPC;
    }

#pragma unroll 1
    for (int kc = 0; kc < HIDD / 32; kc++) {
        CPW(1);
        __syncthreads();
        if (kc + 2 < HIDD / 32) {
            int c = kc + 2;
            float* sA = gs + (c % 3) * GSTG; float* sB = sA + GAWA;
#pragma unroll
            for (int p = 0; p < 4; p++)
                cp16(&sA[(r2 + p * 64) * GST + c2], Ap + (size_t)(p * 64) * HIDD + c * 32);
#pragma unroll
            for (int p = 0; p < 2; p++)
                cp16(&sB[(r2 + p * 64) * GST + c2], Bp + (size_t)(p * 64) * HIDD + c * 32);
        }
        CPC;

        float* sA = gs + (kc % 3) * GSTG;
        float* sB = sA + GAWA;
        const uint32_t sAu = (uint32_t)__cvta_generic_to_shared(sA);
        const uint32_t sBu = (uint32_t)__cvta_generic_to_shared(sB);
#pragma unroll
        for (int ka = 0; ka < 4; ka++) {
            const int kb = ka << 3;
            uint32_t af[4][4], bf[4][2];
#pragma unroll
            for (int mi = 0; mi < 4; mi++)
                ldsm4(af[mi][0], af[mi][1], af[mi][2], af[mi][3],
                      sAu + (uint32_t)(((rowA + mi * 16) * GST + kb + colA) * 4));
#pragma unroll
            for (int p = 0; p < 2; p++)
                ldsm4(bf[2*p][0], bf[2*p][1], bf[2*p+1][0], bf[2*p+1][1],
                      sBu + (uint32_t)(((rowB + p * 16) * GST + kb + colB) * 4));
#pragma unroll
            for (int mi = 0; mi < 4; mi++)
#pragma unroll
                for (int ni = 0; ni < 4; ni++)
                    mma_tf32(acc[mi][ni], af[mi], bf[ni]);
        }
    }

    if (MODE == 0) {
        const int sel = bn >> 11;
        const int h   = (bn & 2047) >> 7;
#pragma unroll
        for (int mi = 0; mi < 4; mi++)
#pragma unroll
            for (int ni = 0; ni < 4; ni++) {
                const int d0 = wn * 32 + ni * 8 + tg * 2;
#pragma unroll
                for (int hr = 0; hr < 2; hr++) {
                    int m = bm + wm * 64 + mi * 16 + g + hr * 8;
                    int b = m >> 11, t = m & 2047;
                    float e = acc[mi][ni][hr * 2 + 0];
                    float o = acc[mi][ni][hr * 2 + 1];
                    if (sel == 2) {
                        // V: transposed layout [bh][d][t]
                        size_t vb = ((size_t)(b * NHH + h) * HDD + d0) * TT + t;
                        g_v[vb]      = rtf(e);
                        g_v[vb + TT] = rtf(o);
                    } else {
                        const float sc = (sel == 0) ? SCALE : 1.f;
                        int i0 = d0 >> 1;
                        float c = cosb[t * 64 + i0], s = sinb[t * 64 + i0];
                        float re = (e * c - o * s) * sc;
                        float ro = (e * s + o * c) * sc;
                        float* dst = (sel == 0) ? g_q : g_k;
                        *(float2*)&dst[((size_t)(b * NHH + h) * TT + t) * HDD + d0] =
                            make_float2(rtf(re), rtf(ro));
                    }
                }
            }
    } else {
#pragma unroll
        for (int mi = 0; mi < 4; mi++)
#pragma unroll
            for (int ni = 0; ni < 4; ni++) {
                const int n = bn + wn * 32 + ni * 8 + tg * 2;
                const float2 bi = *(const float2*)&bias[n];
#pragma unroll
                for (int hr = 0; hr < 2; hr++) {
                    int m = bm + wm * 64 + mi * 16 + g + hr * 8;
                    *(float2*)&Cout[(size_t)m * HIDD + n] =
                        make_float2(acc[mi][ni][hr * 2 + 0] + bi.x,
                                    acc[mi][ni][hr * 2 + 1] + bi.y);
                }
            }
    }
}

// ---------------- Flash attention: K-permuted, V transposed, all-ldmatrix ----
#define AKW (64*132)
#define AVW (128*68)
#define ATTN_WORDS (2*AKW + 2*AVW)
#define ATTN_SMEM (ATTN_WORDS * 4)

__device__ __constant__ int c_kperm[8] = {0, 2, 4, 6, 1, 3, 5, 7};

__global__ __launch_bounds__(256, 1)
void attn_kernel()
{
    extern __shared__ float sm[];
    float* K0 = sm;           float* K1 = sm + AKW;
    float* V0 = sm + 2*AKW;   float* V1 = sm + 2*AKW + AVW;

    const int tid = threadIdx.x;
    const int w = tid >> 5, lane = tid & 31;
    const int g = lane >> 2, tg = lane & 3;
    const int bh = blockIdx.y;
    const size_t base = (size_t)bh * TT * HDD;   // == bh*HDD*TT for V^T
    const int q0 = blockIdx.x << 7;

    const int rowBa = (lane & 7) + (lane >> 4) * 8;
    const int colBa = ((lane >> 3) & 1) * 4;

    // Q fragments in registers
    uint32_t qf[16][4];
    {
        const float* Qp = g_q + base + (size_t)(q0 + w * 16) * HDD;
#pragma unroll
        for (int ka = 0; ka < 16; ka++) {
            qf[ka][0] = __float_as_uint(Qp[g * HDD + ka * 8 + tg]);
            qf[ka][1] = __float_as_uint(Qp[(g + 8) * HDD + ka * 8 + tg]);
            qf[ka][2] = __float_as_uint(Qp[g * HDD + ka * 8 + tg + 4]);
            qf[ka][3] = __float_as_uint(Qp[(g + 8) * HDD + ka * 8 + tg + 4]);
        }
    }

    float oacc[16][4];
#pragma unroll
    for (int n = 0; n < 16; n++)
#pragma unroll
        for (int j = 0; j < 4; j++) oacc[n][j] = 0.f;
    float m0 = -1e30f, m1 = -1e30f, l0 = 0.f, l1 = 0.f;

    {   // stage tile 0
        const float* Kg = g_k + base;
        const float* Vg = g_v + base;      // [d][t] rows, stride TT
#pragma unroll
        for (int u = 0; u < 8; u++) {
            int id = tid + u * 256;
            // K: 64 rows x 32 quads
            int r = id >> 5, cw = (id & 31) << 2;
            int rp = (r & ~7) | c_kperm[r & 7];
            cp16(&K0[rp * 132 + cw], Kg + (size_t)r * HDD + cw);
            // V^T: 128 rows x 16 quads
            int rv = id >> 4, cv = (id & 15) << 2;
            cp16(&V0[rv * 68 + cv], Vg + (size_t)rv * TT + cv);
        }
        CPC;
    }

#pragma unroll 1
    for (int kt = 0; kt < TT / 64; kt++) {
        CPW(0);
        __syncthreads();
        if (kt + 1 < TT / 64) {
            const int k0n = (kt + 1) << 6;
            float* Kd = ((kt + 1) & 1) ? K1 : K0;
            float* Vd = ((kt + 1) & 1) ? V1 : V0;
            const float* Kg = g_k + base + (size_t)k0n * HDD;
            const float* Vg = g_v + base + k0n;
#pragma unroll
            for (int u = 0; u < 8; u++) {
                int id = tid + u * 256;
                int r = id >> 5, cw = (id & 31) << 2;
                int rp = (r & ~7) | c_kperm[r & 7];
                cp16(&Kd[rp * 132 + cw], Kg + (size_t)r * HDD + cw);
                int rv = id >> 4, cv = (id & 15) << 2;
                cp16(&Vd[rv * 68 + cv], Vg + (size_t)rv * TT + cv);
            }
            CPC;
        }
        const float* K = (kt & 1) ? K1 : K0;
        const float* V = (kt & 1) ? V1 : V0;
        const uint32_t Ku = (uint32_t)__cvta_generic_to_shared(K);
        const uint32_t Vu = (uint32_t)__cvta_generic_to_shared(V);

        // S = Q*K^T (16x64 per warp) on permuted K columns
        float sacc[8][4];
#pragma unroll
        for (int n = 0; n < 8; n++)
#pragma unroll
            for (int j = 0; j < 4; j++) sacc[n][j] = 0.f;
#pragma unroll
        for (int ka = 0; ka < 16; ka++) {
            const int kb = ka << 3;
            uint32_t bk[8][2];
#pragma unroll
            for (int p = 0; p < 4; p++)
                ldsm4(bk[2*p][0], bk[2*p][1], bk[2*p+1][0], bk[2*p+1][1],
                      Ku + (uint32_t)(((p * 16 + rowBa) * 132 + kb + colBa) * 4));
#pragma unroll
            for (int n = 0; n < 8; n++)
                mma_tf32(sacc[n], qf[ka], bk[n]);
        }

        // online softmax in registers
        float mx0 = -1e30f, mx1 = -1e30f;
#pragma unroll
        for (int n = 0; n < 8; n++) {
            mx0 = fmaxf(mx0, fmaxf(sacc[n][0], sacc[n][1]));
            mx1 = fmaxf(mx1, fmaxf(sacc[n][2], sacc[n][3]));
        }
        mx0 = fmaxf(mx0, __shfl_xor_sync(0xffffffffu, mx0, 1));
        mx0 = fmaxf(mx0, __shfl_xor_sync(0xffffffffu, mx0, 2));
        mx1 = fmaxf(mx1, __shfl_xor_sync(0xffffffffu, mx1, 1));
        mx1 = fmaxf(mx1, __shfl_xor_sync(0xffffffffu, mx1, 2));
        const float mn0 = fmaxf(m0, mx0), mn1 = fmaxf(m1, mx1);
        const float a0 = __expf(m0 - mn0), a1 = __expf(m1 - mn1);
        float s0 = 0.f, s1 = 0.f;
        uint32_t pf[8][4];
#pragma unroll
        for (int n = 0; n < 8; n++) {
            float p00 = __expf(sacc[n][0] - mn0);
            float p01 = __expf(sacc[n][1] - mn0);
            float p10 = __expf(sacc[n][2] - mn1);
            float p11 = __expf(sacc[n][3] - mn1);
            s0 += p00 + p01; s1 += p10 + p11;
            pf[n][0] = f2tf(p00); pf[n][1] = f2tf(p10);
            pf[n][2] = f2tf(p01); pf[n][3] = f2tf(p11);
        }
        s0 += __shfl_xor_sync(0xffffffffu, s0, 1);
        s0 += __shfl_xor_sync(0xffffffffu, s0, 2);
        s1 += __shfl_xor_sync(0xffffffffu, s1, 1);
        s1 += __shfl_xor_sync(0xffffffffu, s1, 2);
        l0 = l0 * a0 + s0; l1 = l1 * a1 + s1;
        m0 = mn0; m1 = mn1;
#pragma unroll
        for (int n = 0; n < 16; n++) {
            oacc[n][0] *= a0; oacc[n][1] *= a0;
            oacc[n][2] *= a1; oacc[n][3] *= a1;
        }

        // O += P*V : P from registers, V^T fragments via ldmatrix
#pragma unroll
        for (int ka = 0; ka < 8; ka++) {
            uint32_t bv[16][2];
#pragma unroll
            for (int p = 0; p < 8; p++)
                ldsm4(bv[2*p][0], bv[2*p][1], bv[2*p+1][0], bv[2*p+1][1],
                      Vu + (uint32_t)(((p * 16 + rowBa) * 68 + ka * 8 + colBa) * 4));
#pragma unroll
            for (int n = 0; n < 16; n++)
                mma_tf32(oacc[n], pf[ka], bv[n]);
        }
    }

    // epilogue: normalize, round, write [b][t][hid]
    {
        const int b = bh >> 4, h = bh & 15;
        const int t0 = q0 + w * 16 + g, t1 = t0 + 8;
        const float i0 = 1.f / l0, i1 = 1.f / l1;
        float* O0 = g_attn + (size_t)(b * TT + t0) * HIDD + h * HDD;
        float* O1 = g_attn + (size_t)(b * TT + t1) * HIDD + h * HDD;
#pragma unroll
        for (int n = 0; n < 16; n++) {
            int d = n * 8 + tg * 2;
            *(float2*)&O0[d] = make_float2(rtf(oacc[n][0] * i0), rtf(oacc[n][1] * i0));
            *(float2*)&O1[d] = make_float2(rtf(oacc[n][2] * i1), rtf(oacc[n][3] * i1));
        }
    }
}

// ---------------------------------------------------------------------------
extern "C" void kernel_launch(void* const* d_in, const int* in_sizes, int n_in,
                              void* d_out, int out_size)
{
    (void)in_sizes; (void)n_in; (void)out_size;
    const float* x      = (const float*)d_in[0];
    const float* w_qkv  = (const float*)d_in[1];
    const float* w_proj = (const float*)d_in[2];
    const float* b_proj = (const float*)d_in[3];
    const float* cosb   = (const float*)d_in[4];
    const float* sinb   = (const float*)d_in[5];
    float* out = (float*)d_out;

    cudaFuncSetAttribute(attn_kernel,
        cudaFuncAttributeMaxDynamicSharedMemorySize, ATTN_SMEM);
    cudaFuncSetAttribute(gemm_tf32<0>,
        cudaFuncAttributeMaxDynamicSharedMemorySize, GEMM_SMEM);
    cudaFuncSetAttribute(gemm_tf32<1>,
        cudaFuncAttributeMaxDynamicSharedMemorySize, GEMM_SMEM);

    float *gx, *gw1, *gw2;
    cudaGetSymbolAddress((void**)&gx,  g_x);
    cudaGetSymbolAddress((void**)&gw1, g_w1);
    cudaGetSymbolAddress((void**)&gw2, g_w2);

    round_k<<<NX  / 1024, 256>>>(x,      gx);
    round_k<<<NW1 / 1024, 256>>>(w_qkv,  gw1);
    round_k<<<NW2 / 1024, 256>>>(w_proj, gw2);

    dim3 g0(NQKV / 128, MTOT / 256);
    gemm_tf32<0><<<g0, 512, GEMM_SMEM>>>(cosb, sinb, nullptr, nullptr);

    dim3 ga(TT / 128, BB * NHH);
    attn_kernel<<<ga, 256, ATTN_SMEM>>>();

    dim3 g1(HIDD / 128, MTOT / 256);
    gemm_tf32<1><<<g1, 512, GEMM_SMEM>>>(nullptr, nullptr, b_proj, out);
}